// round 6
// baseline (speedup 1.0000x reference)
#include <cuda_runtime.h>
#include <cuda_bf16.h>
#include <cstdint>

// MotionLoss: per-row small-angle HTM chain + global MSE reduction.
// inputs  : [512,1024,18] f32   (d_in[0])   -> TMA bulk path
// targets : [512,1024, 7] f32   (d_in[1])   -> cp.async (LDGSTS) path
// out     : scalar f32
//
// Hypothesis under test: per-SM outstanding-request budgets are per-path;
// splitting traffic across TMA + LDGSTS engines should add bandwidth.

#define TPB 256
#define ROWS_TILE 256
#define NSTAGE 4
#define NBLK 296                       // 2 CTAs/SM * 148 SMs

#define TILE_IN_FLOATS (ROWS_TILE * 18)        // 4608
#define TILE_TG_FLOATS (ROWS_TILE * 7)         // 1792
#define TILE_FLOATS    (ROWS_TILE * 25)        // 6400
#define TILE_IN_BYTES  (TILE_IN_FLOATS * 4)    // 18432
#define TILE_TG_F4     (TILE_TG_FLOATS / 4)    // 448 float4

__device__ float g_partials[NBLK];
__device__ unsigned int g_ticket = 0;

__device__ __forceinline__ uint32_t smem_u32(const void* p) {
    return (uint32_t)__cvta_generic_to_shared(p);
}
__device__ __forceinline__ void mbar_init(uint32_t addr, uint32_t count) {
    asm volatile("mbarrier.init.shared.b64 [%0], %1;" :: "r"(addr), "r"(count) : "memory");
}
__device__ __forceinline__ void mbar_expect_tx(uint32_t addr, uint32_t bytes) {
    asm volatile("mbarrier.arrive.expect_tx.shared.b64 _, [%0], %1;"
                 :: "r"(addr), "r"(bytes) : "memory");
}
__device__ __forceinline__ void bulk_g2s(uint32_t dst, const void* src,
                                         uint32_t bytes, uint32_t mbar) {
    asm volatile(
        "cp.async.bulk.shared::cluster.global.mbarrier::complete_tx::bytes "
        "[%0], [%1], %2, [%3];"
        :: "r"(dst), "l"(src), "r"(bytes), "r"(mbar) : "memory");
}
__device__ __forceinline__ void mbar_wait(uint32_t addr, uint32_t parity) {
    uint32_t done;
    asm volatile(
        "{\n\t.reg .pred p;\n\t"
        "mbarrier.try_wait.parity.acquire.cta.shared::cta.b64 p, [%1], %2;\n\t"
        "selp.b32 %0, 1, 0, p;\n\t}"
        : "=r"(done) : "r"(addr), "r"(parity) : "memory");
    if (!done) {
        asm volatile(
            "{\n\t.reg .pred P1;\n\t"
            "WAIT_LOOP_%=:\n\t"
            "mbarrier.try_wait.parity.acquire.cta.shared::cta.b64 P1, [%0], %1, 0x989680;\n\t"
            "@P1 bra.uni WAIT_DONE_%=;\n\t"
            "bra.uni WAIT_LOOP_%=;\n\t"
            "WAIT_DONE_%=:\n\t}"
            :: "r"(addr), "r"(parity) : "memory");
    }
}
__device__ __forceinline__ void cp_async16(uint32_t saddr, const void* gptr) {
    asm volatile("cp.async.cg.shared.global [%0], [%1], 16;" :: "r"(saddr), "l"(gptr));
}
__device__ __forceinline__ void cp_commit() {
    asm volatile("cp.async.commit_group;");
}
template <int N>
__device__ __forceinline__ void cp_wait() {
    asm volatile("cp.async.wait_group %0;" :: "n"(N));
}

__global__ __launch_bounds__(TPB) void motion_loss_dual(
    const float* __restrict__ in, const float* __restrict__ tgt,
    float* __restrict__ out, int n_rows)
{
    extern __shared__ float smem[];                 // [NSTAGE*TILE_FLOATS] + barriers
    uint64_t* mbar = (uint64_t*)(smem + NSTAGE * TILE_FLOATS);

    const int T = n_rows / ROWS_TILE;               // 2048 full tiles
    const int bid = blockIdx.x;
    const int tid = threadIdx.x;

    if (tid == 0) {
        #pragma unroll
        for (int s = 0; s < NSTAGE; ++s) mbar_init(smem_u32(&mbar[s]), 1);
    }
    asm volatile("fence.proxy.async.shared::cta;" ::: "memory");
    __syncthreads();

    // inputs via TMA (tid0); targets via cp.async (all threads)
    auto issue_tile = [&](int tile, int slot) {
        uint32_t dst = smem_u32(smem + slot * TILE_FLOATS);
        if (tid == 0) {
            uint32_t bar = smem_u32(&mbar[slot]);
            mbar_expect_tx(bar, TILE_IN_BYTES);
            bulk_g2s(dst, in + (size_t)tile * TILE_IN_FLOATS, TILE_IN_BYTES, bar);
        }
        const float* tgb = tgt + (size_t)tile * TILE_TG_FLOATS;
        uint32_t tdst = dst + TILE_IN_BYTES * 1u;   // targets region
        #pragma unroll
        for (int i = 0; i < (TILE_TG_F4 + TPB - 1) / TPB; ++i) {   // 2 iters
            int g = i * TPB + tid;
            if (g < TILE_TG_F4) cp_async16(tdst + g * 16, tgb + g * 4);
        }
        cp_commit();   // every thread commits (keeps group counts aligned)
    };

    // ---- prologue ----
    for (int it = 0; it < NSTAGE - 1; ++it) {
        int tile = bid + it * NBLK;
        if (tile < T) issue_tile(tile, it);
        else cp_commit();
    }

    // ---- main loop ----
    float acc = 0.0f;
    int it = 0;
    for (int tile = bid; tile < T; tile += NBLK, ++it) {
        const int slot = it % NSTAGE;
        const uint32_t parity = (uint32_t)((it / NSTAGE) & 1);
        mbar_wait(smem_u32(&mbar[slot]), parity);   // TMA inputs landed
        cp_wait<NSTAGE - 2>();                      // cp.async targets landed
        __syncthreads();                            // cross-thread visibility

        const float* vp = &smem[slot * TILE_FLOATS + tid * 18];
        const float* t  = &smem[slot * TILE_FLOATS + TILE_IN_FLOATS + tid * 7];

        // float2 reads: 9 conflict-free LDS.64 (72B row stride, 8B aligned)
        const float2* v2 = (const float2*)vp;
        float2 q0 = v2[0], q1 = v2[1], q2 = v2[2], q3 = v2[3], q4 = v2[4];
        float2 q5 = v2[5], q6 = v2[6], q7 = v2[7], q8 = v2[8];
        const float p0 = q0.x, p1 = q0.y, p2 = q1.x;
        const float s00 = q1.y, s01 = q2.x;
        const float s10 = q2.y, s11 = q3.x;
        const float s20 = q3.y, s21 = q4.x;
        const float exX = q4.y, eyX = q5.x, ezX = q5.y;
        const float exY = q6.x, eyY = q6.y, ezY = q7.x;
        const float exZ = q7.y, eyZ = q8.x, ezZ = q8.y;

        const float x = t[4], y = t[5], z = t[6];

        // w = MX * (MY * (MZ * P)), P=(x,y,z,1)
        float ax = x - ezZ * y + eyZ * z + s20;
        float ay = ezZ * x + y - exZ * z + s21;
        float az = -eyZ * x + exZ * y + z + p2;
        float bx = ax - ezY * ay + eyY * az + s10;
        float by = ezY * ax + ay - exY * az + p1;
        float bz = -eyY * ax + exY * ay + az + s11;
        float cx = bx - ezX * by + eyX * bz + p0;
        float cy = ezX * bx + by - exX * bz + s00;
        float cz = -eyX * bx + exX * by + bz + s01;

        const float m1 = cx - x;
        const float m2 = cy - y;
        const float m3 = cz - z;
        const float err = sqrtf(m1 * m1 + m2 * m2 + m3 * m3 + 1e-12f);

        const float d0 = err - t[0];
        const float d1 = m1 - t[1];
        const float d2 = m2 - t[2];
        const float d3 = m3 - t[3];
        acc += d0 * d0 + d1 * d1 + d2 * d2 + d3 * d3;

        __syncthreads();            // readers done before slot reuse

        int nxt_it = it + NSTAGE - 1;
        int nxt_tile = bid + nxt_it * NBLK;
        if (nxt_tile < T) issue_tile(nxt_tile, nxt_it % NSTAGE);
        else cp_commit();
    }
    cp_wait<0>();

    // ---- block reduction (deterministic) ----
    #pragma unroll
    for (int off = 16; off > 0; off >>= 1)
        acc += __shfl_down_sync(0xFFFFFFFFu, acc, off);

    __shared__ float s_warp[TPB / 32];
    const int lane = tid & 31;
    const int wid  = tid >> 5;
    if (lane == 0) s_warp[wid] = acc;
    __syncthreads();
    if (wid == 0) {
        float a = (lane < TPB / 32) ? s_warp[lane] : 0.0f;
        #pragma unroll
        for (int off = 4; off > 0; off >>= 1)
            a += __shfl_down_sync(0xFFFFFFFFu, a, off);
        if (lane == 0) g_partials[bid] = a;
    }

    // ---- last-block-done final reduce ----
    __shared__ bool s_last;
    __threadfence();
    if (tid == 0) {
        unsigned int tk = atomicAdd(&g_ticket, 1u);
        s_last = (tk == gridDim.x - 1);
    }
    __syncthreads();
    if (!s_last) return;

    double sum = 0.0;
    for (int i = tid; i < (int)gridDim.x; i += TPB)
        sum += (double)__ldcg(&g_partials[i]);

    if (tid == 0) {   // remainder rows (none for 512*1024; safety)
        for (int r = T * ROWS_TILE; r < n_rows; ++r) {
            const float* v = in + (size_t)r * 18;
            const float* t = tgt + (size_t)r * 7;
            float x = t[4], y = t[5], z = t[6];
            float ax = x - v[17]*y + v[16]*z + v[7];
            float ay = v[17]*x + y - v[15]*z + v[8];
            float az = -v[16]*x + v[15]*y + z + v[2];
            float bx = ax - v[14]*ay + v[13]*az + v[5];
            float by = v[14]*ax + ay - v[12]*az + v[1];
            float bz = -v[13]*ax + v[12]*ay + az + v[6];
            float cx = bx - v[11]*by + v[10]*bz + v[0];
            float cy = v[11]*bx + by - v[9]*bz + v[3];
            float cz = -v[10]*bx + v[9]*by + bz + v[4];
            float m1 = cx - x, m2 = cy - y, m3 = cz - z;
            float err = sqrtf(m1*m1 + m2*m2 + m3*m3 + 1e-12f);
            float d0 = err - t[0], d1 = m1 - t[1], d2 = m2 - t[2], d3 = m3 - t[3];
            sum += (double)(d0*d0 + d1*d1 + d2*d2 + d3*d3);
        }
    }

    __shared__ double s_fin[TPB];
    s_fin[tid] = sum;
    __syncthreads();
    #pragma unroll
    for (int off = TPB / 2; off > 0; off >>= 1) {
        if (tid < off) s_fin[tid] += s_fin[tid + off];
        __syncthreads();
    }
    if (tid == 0) {
        out[0] = (float)(s_fin[0] / ((double)n_rows * 4.0));
        g_ticket = 0;   // reset for next graph replay
    }
}

extern "C" void kernel_launch(void* const* d_in, const int* in_sizes, int n_in,
                              void* d_out, int out_size)
{
    const float* inputs  = (const float*)d_in[0];
    const float* targets = (const float*)d_in[1];
    float* out = (float*)d_out;

    const int n_rows = in_sizes[0] / 18;                       // 524288
    const int smem_bytes = NSTAGE * TILE_FLOATS * 4 + NSTAGE * 8;   // 102432

    static bool attr_set = false;
    if (!attr_set) {
        cudaFuncSetAttribute(motion_loss_dual,
                             cudaFuncAttributeMaxDynamicSharedMemorySize,
                             smem_bytes);
        attr_set = true;
    }

    motion_loss_dual<<<NBLK, TPB, smem_bytes>>>(inputs, targets, out, n_rows);
}